// round 1
// baseline (speedup 1.0000x reference)
#include <cuda_runtime.h>
#include <math.h>

#define B_  8
#define S_  1024
#define H_  512
#define NH_ 8
#define HD_ 64

// Scratch (device globals: allocation-free). Values stored already tf32-quantized.
__device__ float g_q [B_*NH_*S_*HD_];   // [B,NH,S,HD], pre-scaled by 1/sqrt(HD)
__device__ float g_k [B_*NH_*S_*HD_];   // [B,NH,S,HD]
__device__ float g_vt[B_*NH_*HD_*S_];   // [B,NH,HD,S] (transposed V)

__device__ __forceinline__ float to_tf32(float x) {
    unsigned u;
    asm("cvt.rna.tf32.f32 %0, %1;" : "=r"(u) : "f"(x));
    return __uint_as_float(u);
}

// D = A(16x8,row) * B(8x8,col) + D, tf32 inputs, f32 accum
__device__ __forceinline__ void mma8(float c[4], const float a[4], const float b[2]) {
    asm volatile(
        "mma.sync.aligned.m16n8k8.row.col.f32.tf32.tf32.f32 "
        "{%0,%1,%2,%3}, {%4,%5,%6,%7}, {%8,%9}, {%0,%1,%2,%3};\n"
        : "+f"(c[0]), "+f"(c[1]), "+f"(c[2]), "+f"(c[3])
        : "r"(__float_as_uint(a[0])), "r"(__float_as_uint(a[1])),
          "r"(__float_as_uint(a[2])), "r"(__float_as_uint(a[3])),
          "r"(__float_as_uint(b[0])), "r"(__float_as_uint(b[1])));
}

// ---------------------------------------------------------------------------
// Projection: out[m,n] = sum_k X[m,k] * W[n,k] + bias[n]
// grid: (M/128, N/64, 3)  block: 256 (8 warps, 4x2 warp grid, 32x32 per warp)
// ---------------------------------------------------------------------------
__global__ __launch_bounds__(256) void proj_kernel(
    const float* __restrict__ X,
    const float* __restrict__ Wq, const float* __restrict__ bq,
    const float* __restrict__ Wk, const float* __restrict__ bk,
    const float* __restrict__ Wv, const float* __restrict__ bv)
{
    __shared__ float Xs[128][36];
    __shared__ float Ws[64][36];

    const int zw = blockIdx.z;
    const float* W  = (zw == 0) ? Wq : (zw == 1) ? Wk : Wv;
    const float* bb = (zw == 0) ? bq : (zw == 1) ? bk : bv;

    const int m0 = blockIdx.x * 128;
    const int n0 = blockIdx.y * 64;
    const int tid  = threadIdx.x;
    const int lane = tid & 31;
    const int wid  = tid >> 5;
    const int wm = (wid & 3) * 32;   // warp m offset
    const int wn = (wid >> 2) * 32;  // warp n offset
    const int g = lane >> 2;         // groupID (row within frag)
    const int t = lane & 3;          // threadID in group

    float acc[2][4][4];
#pragma unroll
    for (int i = 0; i < 2; i++)
#pragma unroll
        for (int j = 0; j < 4; j++)
#pragma unroll
            for (int r = 0; r < 4; r++) acc[i][j][r] = 0.f;

    for (int kc = 0; kc < 512; kc += 32) {
        // X tile 128x32 (1024 float4)
#pragma unroll
        for (int p = 0; p < 4; p++) {
            int idx = tid + p * 256;
            int r = idx >> 3, c = (idx & 7) * 4;
            float4 v = *(const float4*)&X[(m0 + r) * 512 + kc + c];
            Xs[r][c + 0] = to_tf32(v.x); Xs[r][c + 1] = to_tf32(v.y);
            Xs[r][c + 2] = to_tf32(v.z); Xs[r][c + 3] = to_tf32(v.w);
        }
        // W tile 64x32 (512 float4)
#pragma unroll
        for (int p = 0; p < 2; p++) {
            int idx = tid + p * 256;
            int r = idx >> 3, c = (idx & 7) * 4;
            float4 v = *(const float4*)&W[(n0 + r) * 512 + kc + c];
            Ws[r][c + 0] = to_tf32(v.x); Ws[r][c + 1] = to_tf32(v.y);
            Ws[r][c + 2] = to_tf32(v.z); Ws[r][c + 3] = to_tf32(v.w);
        }
        __syncthreads();

#pragma unroll
        for (int kk = 0; kk < 4; kk++) {
            float a[2][4];
#pragma unroll
            for (int i = 0; i < 2; i++) {
                int r = wm + i * 16 + g;
                a[i][0] = Xs[r    ][kk * 8 + t];
                a[i][1] = Xs[r + 8][kk * 8 + t];
                a[i][2] = Xs[r    ][kk * 8 + t + 4];
                a[i][3] = Xs[r + 8][kk * 8 + t + 4];
            }
#pragma unroll
            for (int j = 0; j < 4; j++) {
                float b[2];
                int r = wn + j * 8 + g;
                b[0] = Ws[r][kk * 8 + t];
                b[1] = Ws[r][kk * 8 + t + 4];
#pragma unroll
                for (int i = 0; i < 2; i++) mma8(acc[i][j], a[i], b);
            }
        }
        __syncthreads();
    }

    // Epilogue: bias + scatter into attention-friendly layouts
#pragma unroll
    for (int i = 0; i < 2; i++) {
#pragma unroll
        for (int j = 0; j < 4; j++) {
            int n = n0 + wn + j * 8 + t * 2;
            float b0 = bb[n], b1 = bb[n + 1];
            int h = n >> 6, d = n & 63;
#pragma unroll
            for (int rr = 0; rr < 2; rr++) {
                int m = m0 + wm + i * 16 + g + rr * 8;
                int bI = m >> 10, s = m & 1023;
                float v0 = acc[i][j][rr * 2 + 0] + b0;
                float v1 = acc[i][j][rr * 2 + 1] + b1;
                if (zw == 0) {
                    float* dst = &g_q[(((bI * NH_ + h) * S_) + s) * HD_ + d];
                    dst[0] = to_tf32(v0 * 0.125f);
                    dst[1] = to_tf32(v1 * 0.125f);
                } else if (zw == 1) {
                    float* dst = &g_k[(((bI * NH_ + h) * S_) + s) * HD_ + d];
                    dst[0] = to_tf32(v0);
                    dst[1] = to_tf32(v1);
                } else {
                    g_vt[(((bI * NH_ + h) * HD_) + d    ) * S_ + s] = to_tf32(v0);
                    g_vt[(((bI * NH_ + h) * HD_) + d + 1) * S_ + s] = to_tf32(v1);
                }
            }
        }
    }
}

// ---------------------------------------------------------------------------
// Flash attention with rel bias + additive mask.
// grid: (S/128, NH, B)  block: 256 (8 warps x 16 q-rows)
// ---------------------------------------------------------------------------
__global__ __launch_bounds__(256) void attn_kernel(
    const float* __restrict__ rel,   // [B,NH,S,S]
    const float* __restrict__ mask,  // [B,1,1,S]
    float* __restrict__ out)         // [B,S,H]
{
    __shared__ float Ks [32][68];   // K block:  [s_k local][d]
    __shared__ float Vts[64][36];   // Vt block: [d][s_k local]
    __shared__ float Ps [128][36];  // P:        [q local][s_k local]

    const int b = blockIdx.z, h = blockIdx.y;
    const int q0 = blockIdx.x * 128;
    const int tid  = threadIdx.x;
    const int lane = tid & 31;
    const int wid  = tid >> 5;
    const int wq = wid * 16;         // warp's q-row offset within CTA
    const int g = lane >> 2;
    const int t = lane & 3;

    // Q fragments, resident in registers for the whole CTA lifetime
    float qa[8][4];
    {
        const float* Qp = &g_q[(((size_t)(b * NH_ + h) * S_) + q0 + wq) * HD_];
#pragma unroll
        for (int kk = 0; kk < 8; kk++) {
            qa[kk][0] = Qp[(g    ) * 64 + kk * 8 + t];
            qa[kk][1] = Qp[(g + 8) * 64 + kk * 8 + t];
            qa[kk][2] = Qp[(g    ) * 64 + kk * 8 + t + 4];
            qa[kk][3] = Qp[(g + 8) * 64 + kk * 8 + t + 4];
        }
    }

    float o[8][4];
#pragma unroll
    for (int i = 0; i < 8; i++)
#pragma unroll
        for (int r = 0; r < 4; r++) o[i][r] = 0.f;

    float m0v = -INFINITY, m1v = -INFINITY;
    float l0 = 0.f, l1 = 0.f;

    const float* relbase = rel + ((size_t)((b * NH_ + h) * S_) + q0 + wq) * S_;
    const float* Kbase   = &g_k[((size_t)(b * NH_ + h) * S_) * 64];
    const float* Vbase   = &g_vt[((size_t)(b * NH_ + h) * 64) * S_];

    for (int kb = 0; kb < S_; kb += 32) {
        // Load K tile 32x64 (512 float4)
#pragma unroll
        for (int p = 0; p < 2; p++) {
            int idx = tid + p * 256;
            int r = idx >> 4, c = (idx & 15) * 4;
            float4 v = *(const float4*)&Kbase[(kb + r) * 64 + c];
            Ks[r][c] = v.x; Ks[r][c + 1] = v.y; Ks[r][c + 2] = v.z; Ks[r][c + 3] = v.w;
        }
        // Load Vt tile 64x32 (512 float4)
#pragma unroll
        for (int p = 0; p < 2; p++) {
            int idx = tid + p * 256;
            int r = idx >> 3, c = (idx & 7) * 4;
            float4 v = *(const float4*)&Vbase[(size_t)r * S_ + kb + c];
            Vts[r][c] = v.x; Vts[r][c + 1] = v.y; Vts[r][c + 2] = v.z; Vts[r][c + 3] = v.w;
        }
        __syncthreads();

        // S = Q * K^T  (16 x 32 per warp)
        float s[4][4];
#pragma unroll
        for (int nf = 0; nf < 4; nf++) {
#pragma unroll
            for (int r = 0; r < 4; r++) s[nf][r] = 0.f;
#pragma unroll
            for (int kk = 0; kk < 8; kk++) {
                float bf[2];
                int r = nf * 8 + g;
                bf[0] = Ks[r][kk * 8 + t];
                bf[1] = Ks[r][kk * 8 + t + 4];
                mma8(s[nf], qa[kk], bf);
            }
        }

        // + rel bias + attention mask (fp32)
#pragma unroll
        for (int nf = 0; nf < 4; nf++) {
            int col = kb + nf * 8 + t * 2;
            float mk0 = mask[b * S_ + col];
            float mk1 = mask[b * S_ + col + 1];
            const float* rp0 = relbase + (size_t)(g    ) * S_ + col;
            const float* rp1 = relbase + (size_t)(g + 8) * S_ + col;
            s[nf][0] += rp0[0] + mk0;  s[nf][1] += rp0[1] + mk1;
            s[nf][2] += rp1[0] + mk0;  s[nf][3] += rp1[1] + mk1;
        }

        // Online softmax
        float tm0 = -INFINITY, tm1 = -INFINITY;
#pragma unroll
        for (int nf = 0; nf < 4; nf++) {
            tm0 = fmaxf(tm0, fmaxf(s[nf][0], s[nf][1]));
            tm1 = fmaxf(tm1, fmaxf(s[nf][2], s[nf][3]));
        }
        tm0 = fmaxf(tm0, __shfl_xor_sync(0xffffffffu, tm0, 1));
        tm0 = fmaxf(tm0, __shfl_xor_sync(0xffffffffu, tm0, 2));
        tm1 = fmaxf(tm1, __shfl_xor_sync(0xffffffffu, tm1, 1));
        tm1 = fmaxf(tm1, __shfl_xor_sync(0xffffffffu, tm1, 2));

        float mn0 = fmaxf(m0v, tm0), mn1 = fmaxf(m1v, tm1);
        float sc0 = __expf(m0v - mn0), sc1 = __expf(m1v - mn1);
        m0v = mn0; m1v = mn1;

        float rs0 = 0.f, rs1 = 0.f;
#pragma unroll
        for (int nf = 0; nf < 4; nf++) {
            s[nf][0] = __expf(s[nf][0] - mn0);
            s[nf][1] = __expf(s[nf][1] - mn0);
            s[nf][2] = __expf(s[nf][2] - mn1);
            s[nf][3] = __expf(s[nf][3] - mn1);
            rs0 += s[nf][0] + s[nf][1];
            rs1 += s[nf][2] + s[nf][3];
        }
        l0 = l0 * sc0 + rs0;
        l1 = l1 * sc1 + rs1;

        // Rescale running O
#pragma unroll
        for (int nf = 0; nf < 8; nf++) {
            o[nf][0] *= sc0; o[nf][1] *= sc0;
            o[nf][2] *= sc1; o[nf][3] *= sc1;
        }

        // P -> SMEM (tf32-quantized), warp-local region
#pragma unroll
        for (int nf = 0; nf < 4; nf++) {
            int c = nf * 8 + t * 2;
            Ps[wq + g    ][c    ] = to_tf32(s[nf][0]);
            Ps[wq + g    ][c + 1] = to_tf32(s[nf][1]);
            Ps[wq + g + 8][c    ] = to_tf32(s[nf][2]);
            Ps[wq + g + 8][c + 1] = to_tf32(s[nf][3]);
        }
        __syncwarp();

        // O += P * V
#pragma unroll
        for (int kk = 0; kk < 4; kk++) {
            float a[4];
            a[0] = Ps[wq + g    ][kk * 8 + t];
            a[1] = Ps[wq + g + 8][kk * 8 + t];
            a[2] = Ps[wq + g    ][kk * 8 + t + 4];
            a[3] = Ps[wq + g + 8][kk * 8 + t + 4];
#pragma unroll
            for (int nf = 0; nf < 8; nf++) {
                float bf[2];
                bf[0] = Vts[nf * 8 + g][kk * 8 + t];
                bf[1] = Vts[nf * 8 + g][kk * 8 + t + 4];
                mma8(o[nf], a, bf);
            }
        }
        __syncthreads();
    }

    // Final normalization + store
    l0 += __shfl_xor_sync(0xffffffffu, l0, 1);
    l0 += __shfl_xor_sync(0xffffffffu, l0, 2);
    l1 += __shfl_xor_sync(0xffffffffu, l1, 1);
    l1 += __shfl_xor_sync(0xffffffffu, l1, 2);
    float inv0 = 1.f / l0, inv1 = 1.f / l1;

    int q = q0 + wq + g;
    float* ob0 = &out[((size_t)(b * S_ + q    )) * H_ + h * 64];
    float* ob1 = &out[((size_t)(b * S_ + q + 8)) * H_ + h * 64];
#pragma unroll
    for (int nf = 0; nf < 8; nf++) {
        int c = nf * 8 + t * 2;
        ob0[c] = o[nf][0] * inv0;  ob0[c + 1] = o[nf][1] * inv0;
        ob1[c] = o[nf][2] * inv1;  ob1[c + 1] = o[nf][3] * inv1;
    }
}

// ---------------------------------------------------------------------------
// metadata order: hidden_states, attention_mask, rel_2d_pos, Wq, bq, Wk, bk, Wv, bv
// ---------------------------------------------------------------------------
extern "C" void kernel_launch(void* const* d_in, const int* in_sizes, int n_in,
                              void* d_out, int out_size)
{
    const float* hidden = (const float*)d_in[0];
    const float* mask   = (const float*)d_in[1];
    const float* rel    = (const float*)d_in[2];
    const float* Wq     = (const float*)d_in[3];
    const float* bq     = (const float*)d_in[4];
    const float* Wk     = (const float*)d_in[5];
    const float* bk     = (const float*)d_in[6];
    const float* Wv     = (const float*)d_in[7];
    const float* bv     = (const float*)d_in[8];
    float* out = (float*)d_out;

    dim3 pg(64, 8, 3);   // M/128, N/64, {q,k,v}
    proj_kernel<<<pg, 256>>>(hidden, Wq, bq, Wk, bk, Wv, bv);

    dim3 ag(8, NH_, B_); // S/128, NH, B
    attn_kernel<<<ag, 256>>>(rel, mask, out);
}